// round 2
// baseline (speedup 1.0000x reference)
#include <cuda_runtime.h>

#define Bv 16
#define Tt 256
#define Nn 32
#define Ii 64
#define Hh 128
#define G4 512   // 4*H

// Scratch: gates_x[t][b][n][g], and cell state c[b][n*H + h].
// (Static __device__ globals are the sanctioned scratch mechanism.)
__device__ float g_gx[Tt * Bv * Nn * G4];   // 67,108,864 floats = 256 MiB
__device__ float g_c[Bv * Nn * Hh];         // 65,536 floats

// ---------------------------------------------------------------------------
// Kernel 1: gates_x[t][b][n][g] = b_ih[n][g] + b_hh[n][g]
//                                 + sum_i x[b][t][n*64+i] * W_ih[n][g][i]
// grid (64, 32): blockIdx.x = tile of 64 (b,t) pairs, blockIdx.y = n.
// 128 threads, thread tile = 4 bt x 8 g, smem transposed tiles [i][*].
// ---------------------------------------------------------------------------
__global__ void __launch_bounds__(128) gates_x_kernel(
    const float* __restrict__ x,
    const float* __restrict__ W_ih,
    const float* __restrict__ b_ih,
    const float* __restrict__ b_hh)
{
    __shared__ __align__(16) float x_sm[64 * 68];  // [i][bt], stride 68 (pad)
    __shared__ __align__(16) float w_sm[64 * 68];  // [i][g],  stride 68 (pad)

    const int n   = blockIdx.y;
    const int bt0 = blockIdx.x * 64;
    const int tid = threadIdx.x;

    // Load x tile transposed: global rows contiguous in i -> x_sm[i][bt]
    for (int f = tid; f < 4096; f += 128) {
        const int bt = f >> 6, i = f & 63;
        x_sm[i * 68 + bt] = x[(size_t)(bt0 + bt) * (Nn * Ii) + n * Ii + i];
    }

    const float* Wn = W_ih + (size_t)n * G4 * Ii;
    const int btq = tid & 15;  // 16 quads of 4 bt
    const int go  = tid >> 4;  // 8 octets of 8 g

    for (int g0 = 0; g0 < G4; g0 += 64) {
        __syncthreads();  // x_sm ready (iter 0) / previous compute done
        for (int f = tid; f < 4096; f += 128) {
            const int g = f >> 6, i = f & 63;
            w_sm[i * 68 + g] = Wn[(size_t)(g0 + g) * Ii + i];
        }
        __syncthreads();

        float acc[8][4];
#pragma unroll
        for (int a = 0; a < 8; a++)
#pragma unroll
            for (int c = 0; c < 4; c++) acc[a][c] = 0.f;

#pragma unroll 8
        for (int i = 0; i < 64; i++) {
            const float4 xv = *(const float4*)(x_sm + i * 68 + btq * 4);
            const float4 wa = *(const float4*)(w_sm + i * 68 + go * 8);
            const float4 wb = *(const float4*)(w_sm + i * 68 + go * 8 + 4);
            float xr[4] = {xv.x, xv.y, xv.z, xv.w};
            float wr[8] = {wa.x, wa.y, wa.z, wa.w, wb.x, wb.y, wb.z, wb.w};
#pragma unroll
            for (int a = 0; a < 8; a++)
#pragma unroll
                for (int c = 0; c < 4; c++) acc[a][c] += wr[a] * xr[c];
        }

        // Epilogue: add biases, write to g_gx[t][b][n][g]
        float bs[8];
#pragma unroll
        for (int a = 0; a < 8; a++) {
            const int g = g0 + go * 8 + a;
            bs[a] = b_ih[n * G4 + g] + b_hh[n * G4 + g];
        }
#pragma unroll
        for (int bb = 0; bb < 4; bb++) {
            const int bt = bt0 + btq * 4 + bb;
            const int b  = bt >> 8;     // T = 256
            const int t  = bt & 255;
            float* dst = g_gx + (((size_t)t * Bv + b) * Nn + n) * G4 + g0 + go * 8;
            float4 o0, o1;
            o0.x = acc[0][bb] + bs[0];
            o0.y = acc[1][bb] + bs[1];
            o0.z = acc[2][bb] + bs[2];
            o0.w = acc[3][bb] + bs[3];
            o1.x = acc[4][bb] + bs[4];
            o1.y = acc[5][bb] + bs[5];
            o1.z = acc[6][bb] + bs[6];
            o1.w = acc[7][bb] + bs[7];
            *(float4*)(dst)     = o0;
            *(float4*)(dst + 4) = o1;
        }
    }
}

// ---------------------------------------------------------------------------
// Kernel 2: one LSTM timestep.
// grid (8, 32): blockIdx.y = n, blockIdx.x = 16-wide h-chunk. 64 threads.
// Thread = (4-batch quad bq, single h). Computes all 4 gate dot-products
// over k=0..127 for its 4 batches, then the pointwise cell update.
// h_prev is read from output[:, t-1, :] (t==0: from h0); c is block-private.
// ---------------------------------------------------------------------------
__device__ __forceinline__ float fsig(float v) {
    return 1.f / (1.f + __expf(-v));
}
__device__ __forceinline__ float ftanh(float v) {
    return 1.f - 2.f / (__expf(2.f * v) + 1.f);
}

__global__ void __launch_bounds__(64) lstm_step_kernel(
    const float* __restrict__ W_hh,
    const float* __restrict__ h0,
    const float* __restrict__ c0,
    float* __restrict__ out,
    float* __restrict__ hn,
    float* __restrict__ cn,
    int t)
{
    __shared__ __align__(16) float w_sm[64 * 132];  // [gate*16+hh][k], stride 132
    __shared__ __align__(16) float h_sm[128 * 20];  // [k][b], stride 20

    const int n      = blockIdx.y;
    const int h_base = blockIdx.x * 16;
    const int tid    = threadIdx.x;
    const int warp   = tid >> 5, ln = tid & 31;

    // Load W slice: 64 rows (4 gates x 16 h) of 128 k. Coalesced: one row/warp-op.
    const float* Wn = W_hh + (size_t)n * G4 * Hh;
#pragma unroll
    for (int r = warp; r < 64; r += 2) {
        const int gate = r >> 4, hh = r & 15;
        const float4 v = *(const float4*)(Wn + (size_t)(gate * Hh + h_base + hh) * Hh + ln * 4);
        *(float4*)(w_sm + r * 132 + ln * 4) = v;
    }

    // Load h_prev: h_sm[k][b]
    const float* hs;
    size_t hb;
    if (t == 0) { hs = h0 + n * Hh;                          hb = (size_t)(Nn * Hh); }
    else        { hs = out + (size_t)(t - 1) * (Nn * Hh) + n * Hh; hb = (size_t)Tt * (Nn * Hh); }
    for (int f = tid; f < 2048; f += 64) {
        const int b = f >> 7, k = f & 127;
        h_sm[k * 20 + b] = hs[(size_t)b * hb + k];
    }
    __syncthreads();

    const int bq = tid & 3;    // 4 quads of 4 batches
    const int hq = tid >> 2;   // 16 h values

    float acc[4][4];           // [gate][batch-in-quad]
#pragma unroll
    for (int g = 0; g < 4; g++)
#pragma unroll
        for (int j = 0; j < 4; j++) acc[g][j] = 0.f;

#pragma unroll 8
    for (int k = 0; k < 128; k++) {
        const float4 hv = *(const float4*)(h_sm + k * 20 + bq * 4);
        const float w0 = w_sm[(0 * 16 + hq) * 132 + k];
        const float w1 = w_sm[(1 * 16 + hq) * 132 + k];
        const float w2 = w_sm[(2 * 16 + hq) * 132 + k];
        const float w3 = w_sm[(3 * 16 + hq) * 132 + k];
        acc[0][0] += w0 * hv.x; acc[0][1] += w0 * hv.y; acc[0][2] += w0 * hv.z; acc[0][3] += w0 * hv.w;
        acc[1][0] += w1 * hv.x; acc[1][1] += w1 * hv.y; acc[1][2] += w1 * hv.z; acc[1][3] += w1 * hv.w;
        acc[2][0] += w2 * hv.x; acc[2][1] += w2 * hv.y; acc[2][2] += w2 * hv.z; acc[2][3] += w2 * hv.w;
        acc[3][0] += w3 * hv.x; acc[3][1] += w3 * hv.y; acc[3][2] += w3 * hv.z; acc[3][3] += w3 * hv.w;
    }

    const int h = h_base + hq;
#pragma unroll
    for (int j = 0; j < 4; j++) {
        const int b = bq * 4 + j;
        const float* gxp = g_gx + (((size_t)t * Bv + b) * Nn + n) * G4;
        const float gi = acc[0][j] + gxp[0 * Hh + h];
        const float gf = acc[1][j] + gxp[1 * Hh + h];
        const float gg = acc[2][j] + gxp[2 * Hh + h];
        const float go = acc[3][j] + gxp[3 * Hh + h];
        const size_t sidx = (size_t)b * (Nn * Hh) + n * Hh + h;
        const float cprev = (t == 0) ? c0[sidx] : g_c[sidx];
        const float si = fsig(gi), sf = fsig(gf), so = fsig(go);
        const float tg = ftanh(gg);
        const float cv = sf * cprev + si * tg;
        const float hv = so * ftanh(cv);
        out[((size_t)b * Tt + t) * (Nn * Hh) + n * Hh + h] = hv;
        g_c[sidx] = cv;
        if (t == Tt - 1) {
            hn[sidx] = hv;
            cn[sidx] = cv;
        }
    }
}

// ---------------------------------------------------------------------------
extern "C" void kernel_launch(void* const* d_in, const int* in_sizes, int n_in,
                              void* d_out, int out_size)
{
    const float* x    = (const float*)d_in[0];
    const float* h0   = (const float*)d_in[1];
    const float* c0   = (const float*)d_in[2];
    const float* W_ih = (const float*)d_in[3];
    const float* W_hh = (const float*)d_in[4];
    const float* b_ih = (const float*)d_in[5];
    const float* b_hh = (const float*)d_in[6];

    float* out = (float*)d_out;                           // [B,T,N*H]
    float* hn  = out + (size_t)Bv * Tt * Nn * Hh;         // [1,B,N*H]
    float* cn  = hn + (size_t)Bv * Nn * Hh;               // [1,B,N*H]

    gates_x_kernel<<<dim3(64, 32), 128>>>(x, W_ih, b_ih, b_hh);
    for (int t = 0; t < Tt; t++) {
        lstm_step_kernel<<<dim3(8, 32), 64>>>(W_hh, h0, c0, out, hn, cn, t);
    }
}

// round 3
// speedup vs baseline: 1.3963x; 1.3963x over previous
#include <cuda_runtime.h>

#define Bv 16
#define Tt 256
#define Nn 32
#define Ii 64
#define Hh 128
#define G4 512   // 4*H
#define NBLK 256 // persistent grid size (must all be co-resident)

// Scratch: gates_x[t][b][n][g]
__device__ float g_gx[Tt * Bv * Nn * G4];   // 256 MiB
__device__ unsigned g_arrive = 0;           // grid-barrier counter (self-resetting)

// ---------------------------------------------------------------------------
// Kernel 1: gates_x[t][b][n][g] = b_ih[n][g] + b_hh[n][g]
//                                 + sum_i x[b][t][n*64+i] * W_ih[n][g][i]
// ---------------------------------------------------------------------------
__global__ void __launch_bounds__(128) gates_x_kernel(
    const float* __restrict__ x,
    const float* __restrict__ W_ih,
    const float* __restrict__ b_ih,
    const float* __restrict__ b_hh)
{
    __shared__ __align__(16) float x_sm[64 * 68];  // [i][bt]
    __shared__ __align__(16) float w_sm[64 * 68];  // [i][g]

    const int n   = blockIdx.y;
    const int bt0 = blockIdx.x * 64;
    const int tid = threadIdx.x;

    for (int f = tid; f < 4096; f += 128) {
        const int bt = f >> 6, i = f & 63;
        x_sm[i * 68 + bt] = x[(size_t)(bt0 + bt) * (Nn * Ii) + n * Ii + i];
    }

    const float* Wn = W_ih + (size_t)n * G4 * Ii;
    const int btq = tid & 15;
    const int go  = tid >> 4;

    for (int g0 = 0; g0 < G4; g0 += 64) {
        __syncthreads();
        for (int f = tid; f < 4096; f += 128) {
            const int g = f >> 6, i = f & 63;
            w_sm[i * 68 + g] = Wn[(size_t)(g0 + g) * Ii + i];
        }
        __syncthreads();

        float acc[8][4];
#pragma unroll
        for (int a = 0; a < 8; a++)
#pragma unroll
            for (int c = 0; c < 4; c++) acc[a][c] = 0.f;

#pragma unroll 8
        for (int i = 0; i < 64; i++) {
            const float4 xv = *(const float4*)(x_sm + i * 68 + btq * 4);
            const float4 wa = *(const float4*)(w_sm + i * 68 + go * 8);
            const float4 wb = *(const float4*)(w_sm + i * 68 + go * 8 + 4);
            float xr[4] = {xv.x, xv.y, xv.z, xv.w};
            float wr[8] = {wa.x, wa.y, wa.z, wa.w, wb.x, wb.y, wb.z, wb.w};
#pragma unroll
            for (int a = 0; a < 8; a++)
#pragma unroll
                for (int c = 0; c < 4; c++) acc[a][c] += wr[a] * xr[c];
        }

        float bs[8];
#pragma unroll
        for (int a = 0; a < 8; a++) {
            const int g = g0 + go * 8 + a;
            bs[a] = b_ih[n * G4 + g] + b_hh[n * G4 + g];
        }
#pragma unroll
        for (int bb = 0; bb < 4; bb++) {
            const int bt = bt0 + btq * 4 + bb;
            const int b  = bt >> 8;
            const int t  = bt & 255;
            float* dst = g_gx + (((size_t)t * Bv + b) * Nn + n) * G4 + g0 + go * 8;
            float4 o0, o1;
            o0.x = acc[0][bb] + bs[0]; o0.y = acc[1][bb] + bs[1];
            o0.z = acc[2][bb] + bs[2]; o0.w = acc[3][bb] + bs[3];
            o1.x = acc[4][bb] + bs[4]; o1.y = acc[5][bb] + bs[5];
            o1.z = acc[6][bb] + bs[6]; o1.w = acc[7][bb] + bs[7];
            *(float4*)(dst)     = o0;
            *(float4*)(dst + 4) = o1;
        }
    }
}

// ---------------------------------------------------------------------------
// Grid-wide barrier (all NBLK blocks co-resident).
// ---------------------------------------------------------------------------
__device__ __forceinline__ void grid_sync(unsigned target)
{
    __syncthreads();
    if (threadIdx.x == 0) {
        asm volatile("red.release.gpu.global.add.u32 [%0], %1;"
                     :: "l"(&g_arrive), "r"(1u) : "memory");
        unsigned v;
        for (;;) {
            asm volatile("ld.acquire.gpu.global.u32 %0, [%1];"
                         : "=r"(v) : "l"(&g_arrive) : "memory");
            if (v >= target) break;
            __nanosleep(40);
        }
    }
    __syncthreads();
}

__device__ __forceinline__ float fsig(float v) { return 1.f / (1.f + __expf(-v)); }
__device__ __forceinline__ float ftanh(float v) { return 1.f - 2.f / (__expf(2.f * v) + 1.f); }

// ---------------------------------------------------------------------------
// Kernel 2: persistent recurrence. 256 blocks x 128 threads.
// block = (n, 16-wide h chunk). W_hh slice loaded into smem ONCE.
// thread = (hq 0..15, bq 0..7): 4 gates x 2 batches x 1 h. c stays in regs.
// ---------------------------------------------------------------------------
__global__ void __launch_bounds__(128) lstm_persistent(
    const float* __restrict__ W_hh,
    const float* __restrict__ h0,
    const float* __restrict__ c0,
    float* __restrict__ out,
    float* __restrict__ hn,
    float* __restrict__ cn)
{
    __shared__ __align__(16) float w_sm[128 * 64];  // [k][hq][gate]  32 KB
    __shared__ __align__(16) float h_sm[128 * 18];  // [k][b] stride 18

    const int n      = blockIdx.x & 31;
    const int h_base = (blockIdx.x >> 5) * 16;
    const int tid    = threadIdx.x;
    const int hq     = tid >> 3;       // 0..15
    const int bq     = tid & 7;        // 0..7 -> batches 2*bq, 2*bq+1
    const int h      = h_base + hq;

    // --- Load W_hh slice once: w_sm[k*64 + hh*4 + gate] ---
    const float* Wn = W_hh + (size_t)n * G4 * Hh;
    for (int f = tid; f < 8192; f += 128) {
        const int row = f >> 7;           // gate*16 + hh
        const int k   = f & 127;
        const int gate = row >> 4, hh = row & 15;
        w_sm[k * 64 + hh * 4 + gate] =
            Wn[(size_t)(gate * Hh + h_base + hh) * Hh + k];
    }

    // --- Cell state in registers ---
    float creg[2];
#pragma unroll
    for (int j = 0; j < 2; j++) {
        const int b = bq * 2 + j;
        creg[j] = c0[(size_t)b * (Nn * Hh) + n * Hh + h];
    }

    for (int t = 0; t < Tt; t++) {
        // --- Load h_prev into h_sm[k][b] ---
        const float* hs;
        size_t hstr;
        if (t == 0) { hs = h0 + n * Hh;  hstr = (size_t)(Nn * Hh); }
        else        { hs = out + (size_t)(t - 1) * (Nn * Hh) + n * Hh;
                      hstr = (size_t)Tt * (Nn * Hh); }
        __syncthreads();   // previous step's readers done (also covers W load, t=0)
        for (int f = tid; f < 2048; f += 128) {
            const int b = f >> 7, k = f & 127;
            h_sm[k * 18 + b] = hs[(size_t)b * hstr + k];
        }
        __syncthreads();

        // --- 4 gates x 2 batches dot products over k ---
        float acc[4][2];
#pragma unroll
        for (int g = 0; g < 4; g++)
#pragma unroll
            for (int j = 0; j < 2; j++) acc[g][j] = 0.f;

#pragma unroll 8
        for (int k = 0; k < 128; k++) {
            const float2 hv = *(const float2*)(h_sm + k * 18 + bq * 2);
            const float4 wv = *(const float4*)(w_sm + k * 64 + hq * 4);
            acc[0][0] += wv.x * hv.x;  acc[0][1] += wv.x * hv.y;
            acc[1][0] += wv.y * hv.x;  acc[1][1] += wv.y * hv.y;
            acc[2][0] += wv.z * hv.x;  acc[2][1] += wv.z * hv.y;
            acc[3][0] += wv.w * hv.x;  acc[3][1] += wv.w * hv.y;
        }

        // --- Pointwise LSTM update ---
#pragma unroll
        for (int j = 0; j < 2; j++) {
            const int b = bq * 2 + j;
            const float* gxp = g_gx + (((size_t)t * Bv + b) * Nn + n) * G4;
            const float gi = acc[0][j] + gxp[0 * Hh + h];
            const float gf = acc[1][j] + gxp[1 * Hh + h];
            const float gg = acc[2][j] + gxp[2 * Hh + h];
            const float go = acc[3][j] + gxp[3 * Hh + h];
            const float si = fsig(gi), sf = fsig(gf), so = fsig(go);
            const float tg = ftanh(gg);
            const float cv = sf * creg[j] + si * tg;
            const float hv = so * ftanh(cv);
            creg[j] = cv;
            out[((size_t)b * Tt + t) * (Nn * Hh) + n * Hh + h] = hv;
            if (t == Tt - 1) {
                const size_t sidx = (size_t)b * (Nn * Hh) + n * Hh + h;
                hn[sidx] = hv;
                cn[sidx] = cv;
            }
        }

        if (t < Tt - 1) grid_sync((unsigned)(NBLK * (t + 1)));
    }

    // --- Reset barrier counter for the next graph replay ---
    __syncthreads();
    if (tid == 0) {
        const unsigned old = atomicAdd(&g_arrive, 1u);
        if (old == (unsigned)(NBLK * (Tt - 1) + NBLK - 1))
            atomicExch(&g_arrive, 0u);   // last arriver resets
    }
}

// ---------------------------------------------------------------------------
extern "C" void kernel_launch(void* const* d_in, const int* in_sizes, int n_in,
                              void* d_out, int out_size)
{
    const float* x    = (const float*)d_in[0];
    const float* h0   = (const float*)d_in[1];
    const float* c0   = (const float*)d_in[2];
    const float* W_ih = (const float*)d_in[3];
    const float* W_hh = (const float*)d_in[4];
    const float* b_ih = (const float*)d_in[5];
    const float* b_hh = (const float*)d_in[6];

    float* out = (float*)d_out;                           // [B,T,N*H]
    float* hn  = out + (size_t)Bv * Tt * Nn * Hh;         // [1,B,N*H]
    float* cn  = hn + (size_t)Bv * Nn * Hh;               // [1,B,N*H]

    gates_x_kernel<<<dim3(64, 32), 128>>>(x, W_ih, b_ih, b_hh);
    lstm_persistent<<<NBLK, 128>>>(W_hh, h0, c0, out, hn, cn);
}

// round 6
// speedup vs baseline: 2.0905x; 1.4972x over previous
#include <cuda_runtime.h>
#include <cstdint>

#define Bv 16
#define Tt 256
#define Nn 32
#define Ii 64
#define Hh 128
#define G4 512   // 4*H
#define CL 4     // cluster size (CTAs per n), each CTA owns 32 h

// Scratch: gates_x[t][b][n][g]
__device__ float g_gx[Tt * Bv * Nn * G4];   // 256 MiB

// ---------------------------------------------------------------------------
// Packed f32x2 helpers (sm_103a)
// ---------------------------------------------------------------------------
__device__ __forceinline__ unsigned long long pack2(float lo, float hi) {
    unsigned long long r;
    asm("mov.b64 %0, {%1, %2};" : "=l"(r)
        : "r"(__float_as_uint(lo)), "r"(__float_as_uint(hi)));
    return r;
}
__device__ __forceinline__ void unpack2(unsigned long long v, float& lo, float& hi) {
    unsigned a, b;
    asm("mov.b64 {%0, %1}, %2;" : "=r"(a), "=r"(b) : "l"(v));
    lo = __uint_as_float(a); hi = __uint_as_float(b);
}
__device__ __forceinline__ unsigned long long fma2(unsigned long long a,
                                                   unsigned long long b,
                                                   unsigned long long c) {
    unsigned long long d;
    asm("fma.rn.f32x2 %0, %1, %2, %3;" : "=l"(d) : "l"(a), "l"(b), "l"(c));
    return d;
}
__device__ __forceinline__ unsigned long long add2(unsigned long long a,
                                                   unsigned long long b) {
    unsigned long long d;
    asm("add.rn.f32x2 %0, %1, %2;" : "=l"(d) : "l"(a), "l"(b));
    return d;
}

__device__ __forceinline__ float fsig(float v) { return 1.f / (1.f + __expf(-v)); }
__device__ __forceinline__ float ftanh(float v) { return 1.f - 2.f / (__expf(2.f * v) + 1.f); }

// ---------------------------------------------------------------------------
// Kernel 1: gates_x[t][b][n][g] = b_ih[n][g]+b_hh[n][g] + x[b,t,n*64:]·W_ih[n,g,:]
// grid (64, 32), 128 threads; thread tile 4 bt x 8 g, packed over gate-pairs.
// ---------------------------------------------------------------------------
__global__ void __launch_bounds__(128) gates_x_kernel(
    const float* __restrict__ x,
    const float* __restrict__ W_ih,
    const float* __restrict__ b_ih,
    const float* __restrict__ b_hh)
{
    __shared__ __align__(16) float x_sm[64 * 68];  // [i][bt]
    __shared__ __align__(16) float w_sm[64 * 68];  // [i][g]

    const int n   = blockIdx.y;
    const int bt0 = blockIdx.x * 64;
    const int tid = threadIdx.x;

    for (int f = tid; f < 4096; f += 128) {
        const int bt = f >> 6, i = f & 63;
        x_sm[i * 68 + bt] = x[(size_t)(bt0 + bt) * (Nn * Ii) + n * Ii + i];
    }

    const float* Wn = W_ih + (size_t)n * G4 * Ii;
    const int btq = tid & 15;
    const int go  = tid >> 4;

    for (int g0 = 0; g0 < G4; g0 += 64) {
        __syncthreads();
        for (int f = tid; f < 4096; f += 128) {
            const int g = f >> 6, i = f & 63;
            w_sm[i * 68 + g] = Wn[(size_t)(g0 + g) * Ii + i];
        }
        __syncthreads();

        // acc[gp][bt] packed over gate pair (g = go*8 + gp*2 + {0,1})
        unsigned long long acc[4][4];
#pragma unroll
        for (int a = 0; a < 4; a++)
#pragma unroll
            for (int c = 0; c < 4; c++) acc[a][c] = 0ULL;

#pragma unroll 8
        for (int i = 0; i < 64; i++) {
            const float4 xv = *(const float4*)(x_sm + i * 68 + btq * 4);
            const ulonglong2 wA = *(const ulonglong2*)(w_sm + i * 68 + go * 8);
            const ulonglong2 wB = *(const ulonglong2*)(w_sm + i * 68 + go * 8 + 4);
            const unsigned long long xd0 = pack2(xv.x, xv.x);
            const unsigned long long xd1 = pack2(xv.y, xv.y);
            const unsigned long long xd2 = pack2(xv.z, xv.z);
            const unsigned long long xd3 = pack2(xv.w, xv.w);
            acc[0][0] = fma2(wA.x, xd0, acc[0][0]);
            acc[0][1] = fma2(wA.x, xd1, acc[0][1]);
            acc[0][2] = fma2(wA.x, xd2, acc[0][2]);
            acc[0][3] = fma2(wA.x, xd3, acc[0][3]);
            acc[1][0] = fma2(wA.y, xd0, acc[1][0]);
            acc[1][1] = fma2(wA.y, xd1, acc[1][1]);
            acc[1][2] = fma2(wA.y, xd2, acc[1][2]);
            acc[1][3] = fma2(wA.y, xd3, acc[1][3]);
            acc[2][0] = fma2(wB.x, xd0, acc[2][0]);
            acc[2][1] = fma2(wB.x, xd1, acc[2][1]);
            acc[2][2] = fma2(wB.x, xd2, acc[2][2]);
            acc[2][3] = fma2(wB.x, xd3, acc[2][3]);
            acc[3][0] = fma2(wB.y, xd0, acc[3][0]);
            acc[3][1] = fma2(wB.y, xd1, acc[3][1]);
            acc[3][2] = fma2(wB.y, xd2, acc[3][2]);
            acc[3][3] = fma2(wB.y, xd3, acc[3][3]);
        }

        // Packed biases for the 8 gates this thread owns
        unsigned long long bsp[4];
#pragma unroll
        for (int gp = 0; gp < 4; gp++) {
            const int g = g0 + go * 8 + gp * 2;
            const unsigned long long bi = *(const unsigned long long*)(b_ih + n * G4 + g);
            const unsigned long long bh = *(const unsigned long long*)(b_hh + n * G4 + g);
            bsp[gp] = add2(bi, bh);
        }
#pragma unroll
        for (int bb = 0; bb < 4; bb++) {
            const int bt = bt0 + btq * 4 + bb;
            const int b  = bt >> 8;      // T = 256
            const int t  = bt & 255;
            float* dst = g_gx + (((size_t)t * Bv + b) * Nn + n) * G4 + g0 + go * 8;
            ulonglong2 o0, o1;
            o0.x = add2(acc[0][bb], bsp[0]);
            o0.y = add2(acc[1][bb], bsp[1]);
            o1.x = add2(acc[2][bb], bsp[2]);
            o1.y = add2(acc[3][bb], bsp[3]);
            *(ulonglong2*)(dst)     = o0;
            *(ulonglong2*)(dst + 4) = o1;
        }
    }
}

// ---------------------------------------------------------------------------
// Kernel 2: persistent recurrence with CGA clusters. NO grid barrier.
// cluster = 4 CTAs handling one n (32 h each). grid = 128 CTAs x 128 threads.
// thread = (hq 0..15 -> 2 h, bq 0..7 -> 2 batches). c in registers.
// h exchange via DSMEM double buffer + barrier.cluster per step.
// ---------------------------------------------------------------------------
#define WSM_K_STRIDE 132                       // 132*4B = 528 (16B aligned, low conflict)
#define WSM_FLOATS   (128 * WSM_K_STRIDE)      // 16896
#define HSM_FLOATS   (128 * 18)                // one h buffer [k][b], stride 18
#define RSMEM_BYTES  ((WSM_FLOATS + 2 * HSM_FLOATS) * 4)

__global__ void __launch_bounds__(128, 1) __cluster_dims__(CL, 1, 1)
lstm_persistent(const float* __restrict__ W_hh,
                const float* __restrict__ h0,
                const float* __restrict__ c0,
                float* __restrict__ out,
                float* __restrict__ hn,
                float* __restrict__ cn)
{
    extern __shared__ __align__(16) float dsm[];
    float* w_sm = dsm;                  // [k][gp][hql][g2][h2], k-stride 132
    float* h_sm = dsm + WSM_FLOATS;     // 2 x [k 128][b 16 + pad2]

    const int tid = threadIdx.x;
    const int hq  = tid >> 3;           // 0..15 -> h pair
    const int bq  = tid & 7;            // 0..7  -> batches 2bq, 2bq+1
    unsigned rank;
    asm("mov.u32 %0, %%cluster_ctarank;" : "=r"(rank));
    const int n      = blockIdx.x >> 2;
    const int h_base = (int)rank * 32;
    const int hh     = h_base + 2 * hq;

    // Peer SMEM base addresses of h_sm for all cluster ranks
    uint32_t h_sm_u32;
    asm("{ .reg .u64 t; cvta.to.shared.u64 t, %1; cvt.u32.u64 %0, t; }"
        : "=r"(h_sm_u32) : "l"((const void*)h_sm));
    uint32_t peer[CL];
#pragma unroll
    for (int r = 0; r < CL; r++)
        asm("mapa.shared::cluster.u32 %0, %1, %2;"
            : "=r"(peer[r]) : "r"(h_sm_u32), "r"((unsigned)r));

    // --- Load W_hh slice once (rows G = g*128 + h_base + hl), interleaved layout ---
    const float* Wn = W_hh + (size_t)n * G4 * Hh;
#pragma unroll 4
    for (int j = 0; j < 128; j++) {
        const int g = j >> 5, hl = j & 31;
        w_sm[tid * WSM_K_STRIDE + (g >> 1) * 64 + (hl >> 1) * 4 + (g & 1) * 2 + (hl & 1)] =
            Wn[(size_t)(g * Hh + h_base + hl) * Hh + tid];
    }

    // --- Initial h into buffer 0, c into registers ---
    for (int f = tid; f < 2048; f += 128) {
        const int b = f >> 7, k = f & 127;
        h_sm[k * 18 + b] = h0[(size_t)b * (Nn * Hh) + n * Hh + k];
    }
    float creg[2][2];  // [h2][b-in-pair]
#pragma unroll
    for (int h2 = 0; h2 < 2; h2++)
#pragma unroll
        for (int jb = 0; jb < 2; jb++)
            creg[h2][jb] = c0[(size_t)(2 * bq + jb) * (Nn * Hh) + n * Hh + hh + h2];

    __syncthreads();

    for (int t = 0; t < Tt; t++) {
        const float* cons = h_sm + (t & 1) * HSM_FLOATS;
        const uint32_t prodOff = (uint32_t)(((t + 1) & 1) * HSM_FLOATS * 4);

        // Prefetch gates_x for this (t, batches, h-pair): hidden under k-loop
        float2 gx[4][2];
#pragma unroll
        for (int g = 0; g < 4; g++)
#pragma unroll
            for (int jb = 0; jb < 2; jb++)
                gx[g][jb] = *(const float2*)(g_gx +
                    (((size_t)t * Bv + (2 * bq + jb)) * Nn + n) * G4 + g * Hh + hh);

        // acc[gate][b] packed over the h-pair
        unsigned long long acc[4][2];
#pragma unroll
        for (int g = 0; g < 4; g++)
#pragma unroll
            for (int jb = 0; jb < 2; jb++) acc[g][jb] = 0ULL;

#pragma unroll 8
        for (int k = 0; k < 128; k++) {
            const ulonglong2 w01 = *(const ulonglong2*)(w_sm + k * WSM_K_STRIDE + hq * 4);
            const ulonglong2 w23 = *(const ulonglong2*)(w_sm + k * WSM_K_STRIDE + 64 + hq * 4);
            const float2 hv = *(const float2*)(cons + k * 18 + 2 * bq);
            const unsigned long long hb0 = pack2(hv.x, hv.x);
            const unsigned long long hb1 = pack2(hv.y, hv.y);
            acc[0][0] = fma2(w01.x, hb0, acc[0][0]);
            acc[1][0] = fma2(w01.y, hb0, acc[1][0]);
            acc[2][0] = fma2(w23.x, hb0, acc[2][0]);
            acc[3][0] = fma2(w23.y, hb0, acc[3][0]);
            acc[0][1] = fma2(w01.x, hb1, acc[0][1]);
            acc[1][1] = fma2(w01.y, hb1, acc[1][1]);
            acc[2][1] = fma2(w23.x, hb1, acc[2][1]);
            acc[3][1] = fma2(w23.y, hb1, acc[3][1]);
        }

        // --- Pointwise LSTM update for 2h x 2b ---
        float hnew[2][2];  // [h2][b]
#pragma unroll
        for (int jb = 0; jb < 2; jb++) {
            float a[4][2];
#pragma unroll
            for (int g = 0; g < 4; g++) unpack2(acc[g][jb], a[g][0], a[g][1]);
#pragma unroll
            for (int h2 = 0; h2 < 2; h2++) {
                const float gi = a[0][h2] + (h2 ? gx[0][jb].y : gx[0][jb].x);
                const float gf = a[1][h2] + (h2 ? gx[1][jb].y : gx[1][jb].x);
                const float gg = a[2][h2] + (h2 ? gx[2][jb].y : gx[2][jb].x);
                const float go = a[3][h2] + (h2 ? gx[3][jb].y : gx[3][jb].x);
                const float cv = fsig(gf) * creg[h2][jb] + fsig(gi) * ftanh(gg);
                const float hv = fsig(go) * ftanh(cv);
                creg[h2][jb] = cv;
                hnew[h2][jb] = hv;
            }
            // output (fire-and-forget, not on the critical path)
            const int b = 2 * bq + jb;
            *(float2*)(out + ((size_t)b * Tt + t) * (Nn * Hh) + n * Hh + hh) =
                make_float2(hnew[0][jb], hnew[1][jb]);
        }

        if (t < Tt - 1) {
            // DSMEM: deliver produced h to every cluster CTA's next buffer
#pragma unroll
            for (int h2 = 0; h2 < 2; h2++) {
                const unsigned long long val = pack2(hnew[h2][0], hnew[h2][1]);
                const uint32_t off = prodOff + (uint32_t)(((hh + h2) * 18 + 2 * bq) * 4);
#pragma unroll
                for (int r = 0; r < CL; r++)
                    asm volatile("st.shared::cluster.b64 [%0], %1;"
                                 :: "r"(peer[r] + off), "l"(val) : "memory");
            }
            asm volatile("barrier.cluster.arrive.aligned;" ::: "memory");
            asm volatile("barrier.cluster.wait.aligned;"   ::: "memory");
        } else {
#pragma unroll
            for (int jb = 0; jb < 2; jb++) {
                const int b = 2 * bq + jb;
                const size_t sidx = (size_t)b * (Nn * Hh) + n * Hh + hh;
                *(float2*)(hn + sidx) = make_float2(hnew[0][jb], hnew[1][jb]);
                *(float2*)(cn + sidx) = make_float2(creg[0][jb], creg[1][jb]);
            }
        }
    }

    // Keep cluster CTA lifetimes overlapped (peers may still receive our writes)
    asm volatile("barrier.cluster.arrive.aligned;" ::: "memory");
    asm volatile("barrier.cluster.wait.aligned;"   ::: "memory");
}

// ---------------------------------------------------------------------------
extern "C" void kernel_launch(void* const* d_in, const int* in_sizes, int n_in,
                              void* d_out, int out_size)
{
    const float* x    = (const float*)d_in[0];
    const float* h0   = (const float*)d_in[1];
    const float* c0   = (const float*)d_in[2];
    const float* W_ih = (const float*)d_in[3];
    const float* W_hh = (const float*)d_in[4];
    const float* b_ih = (const float*)d_in[5];
    const float* b_hh = (const float*)d_in[6];

    float* out = (float*)d_out;                           // [B,T,N*H]
    float* hn  = out + (size_t)Bv * Tt * Nn * Hh;         // [1,B,N*H]
    float* cn  = hn + (size_t)Bv * Nn * Hh;               // [1,B,N*H]

    static bool attr_done = false;
    if (!attr_done) {
        cudaFuncSetAttribute(lstm_persistent,
                             cudaFuncAttributeMaxDynamicSharedMemorySize,
                             RSMEM_BYTES);
        attr_done = true;
    }

    gates_x_kernel<<<dim3(64, 32), 128>>>(x, W_ih, b_ih, b_hh);
    lstm_persistent<<<Nn * CL, 128, RSMEM_BYTES>>>(W_hh, h0, c0, out, hn, cn);
}